// round 4
// baseline (speedup 1.0000x reference)
#include <cuda_runtime.h>

#define S    512
#define C    192
#define B    2
#define BW   21
#define HALF 10
#define KS   7

#define NPLANES   (B * C)          // 384
#define COPY_BLKS 24576            // 25,165,824 float4 / 1024
#define FAT_BLKS  (NPLANES + COPY_BLKS)

// Scratch (allocation-free rule: __device__ globals)
__device__ float g_conv [NPLANES * S];   // band after depthwise conv
__device__ float g_xdiag[NPLANES * S];   // x[p, j, j] stashed by K1

// ---------------------------------------------------------------------------
// Fat kernel:
//   blocks [0, 384):        K1 — band mean + depthwise conv for one plane,
//                           also stash the plane's diagonal of x.
//   blocks [384, 24960):    pure streaming copy x -> out (4 x float4/thread).
// The two roles are independent; K1 blocks are wave-1 and overlap with the
// bandwidth-bound copy.
// ---------------------------------------------------------------------------
__global__ void __launch_bounds__(256) fat_kernel(
        const float*  __restrict__ x,
        const float*  __restrict__ conv_w,
        const float4* __restrict__ x4,
        float4*       __restrict__ out4) {
    __shared__ float stripe[S * BW];   // 43 KB: stripe[r*21+k] = x[r, r-10+k]
    __shared__ float band[S];

    const int tid = threadIdx.x;

    if (blockIdx.x < NPLANES) {
        // ----------------- K1: band + depthwise conv ------------------------
        const int bc = blockIdx.x;                    // b*C + c
        const int c  = bc % C;
        const float* plane = x + ((size_t)bc << 18);  // bc * S*S

        // Phase 1: load stripe (contiguous 21-elem runs per row).
        #pragma unroll 6
        for (int idx = tid; idx < S * BW; idx += 256) {
            const int r   = idx / BW;
            const int k   = idx - r * BW;
            const int col = r - HALF + k;
            stripe[idx] = (col >= 0 && col < S) ? plane[r * S + col] : 0.f;
        }
        __syncthreads();

        // Phase 2: band[j] = mean_t x[j-10+t, j] = stripe[(j-10+t)*21 + (20-t)]
        #pragma unroll
        for (int j = tid; j < S; j += 256) {
            float sum = 0.f;
            #pragma unroll
            for (int t = 0; t < BW; t++) {
                const int r = j - HALF + t;
                if (r >= 0 && r < S) sum += stripe[r * BW + (BW - 1 - t)];
            }
            band[j] = sum * (1.0f / (float)BW);
            // x[j, j] = stripe row j, k = 10
            g_xdiag[(bc << 9) + j] = stripe[j * BW + HALF];
        }
        __syncthreads();

        // Phase 3: depthwise conv1d, k=7, pad=3
        float w[KS];
        #pragma unroll
        for (int k = 0; k < KS; k++) w[k] = conv_w[c * KS + k];
        #pragma unroll
        for (int j = tid; j < S; j += 256) {
            float acc = 0.f;
            #pragma unroll
            for (int k = 0; k < KS; k++) {
                const int s = j + k - 3;
                if (s >= 0 && s < S) acc += band[s] * w[k];
            }
            g_conv[(bc << 9) + j] = acc;
        }
    } else {
        // ----------------- pure streaming copy ------------------------------
        const int base = (blockIdx.x - NPLANES) * 1024 + tid;
        float4 v0 = __ldcs(x4 + base);
        float4 v1 = __ldcs(x4 + base + 256);
        float4 v2 = __ldcs(x4 + base + 512);
        float4 v3 = __ldcs(x4 + base + 768);
        __stcs(out4 + base,       v0);
        __stcs(out4 + base + 256, v1);
        __stcs(out4 + base + 512, v2);
        __stcs(out4 + base + 768, v3);
    }
}

// ---------------------------------------------------------------------------
// K2 + diagonal fixup: per (b,d) — pointwise GEMV over C + bias + softmax,
// then overwrite the 512 diagonal elements of this output plane.
// ---------------------------------------------------------------------------
__global__ void __launch_bounds__(512) point_softmax_fixup_kernel(
        const float* __restrict__ point_w,
        const float* __restrict__ point_b,
        float*       __restrict__ out) {
    __shared__ float wrow[C];
    __shared__ float red[S];

    const int bd = blockIdx.x;         // b*C + d
    const int b  = bd / C;
    const int d  = bd - b * C;
    const int s  = threadIdx.x;        // 0..511

    if (s < C) wrow[s] = point_w[d * C + s];
    __syncthreads();

    const float* cb = g_conv + b * C * S;
    float acc = point_b[d];
    #pragma unroll 4
    for (int c = 0; c < C; c++)
        acc += cb[c * S + s] * wrow[c];

    // softmax over 512 values in the block
    red[s] = acc;
    __syncthreads();
    #pragma unroll
    for (int off = 256; off > 0; off >>= 1) {
        if (s < off) red[s] = fmaxf(red[s], red[s + off]);
        __syncthreads();
    }
    const float m = red[0];
    __syncthreads();

    const float e = __expf(acc - m);
    red[s] = e;
    __syncthreads();
    #pragma unroll
    for (int off = 256; off > 0; off >>= 1) {
        if (s < off) red[s] += red[s + off];
        __syncthreads();
    }
    const float attn = e / red[0];

    // Diagonal fixup: out[bd, s, s] = x[bd, s, s] * attn
    out[((size_t)bd << 18) + (size_t)s * (S + 1)] =
        g_xdiag[(bd << 9) + s] * attn;
}

// ---------------------------------------------------------------------------
extern "C" void kernel_launch(void* const* d_in, const int* in_sizes, int n_in,
                              void* d_out, int out_size) {
    const float* x       = (const float*)d_in[0];   // [2,192,512,512]
    const float* conv_w  = (const float*)d_in[1];   // [192,1,7]
    const float* point_w = (const float*)d_in[2];   // [192,192]
    const float* point_b = (const float*)d_in[3];   // [192]
    float* out = (float*)d_out;

    fat_kernel<<<FAT_BLKS, 256>>>(x, conv_w, (const float4*)x, (float4*)out);
    point_softmax_fixup_kernel<<<NPLANES, S>>>(point_w, point_b, out);
}

// round 5
// speedup vs baseline: 1.1620x; 1.1620x over previous
#include <cuda_runtime.h>

#define S    512
#define C    192
#define B    2
#define BW   21
#define HALF 10
#define KS   7

#define NPLANES (B * C)            // 384

// Scratch (allocation-free rule: __device__ globals)
__device__ float g_conv[NPLANES * S];   // band after depthwise conv
__device__ float g_attn[NPLANES * S];   // after pointwise + softmax

// ---------------------------------------------------------------------------
// K1: 2 blocks per (b,c) plane, 256 threads. Each block computes 256 band
// outputs (+3 halo for the k=7 conv) from a ~269-row stripe slice (23 KB smem).
// ---------------------------------------------------------------------------
__global__ void __launch_bounds__(256) band_conv_kernel(
        const float* __restrict__ x, const float* __restrict__ conv_w) {
    __shared__ float stripe[270 * BW];   // stripe[(r-r0)*21+k] = x[r, r-10+k]
    __shared__ float band_s[260];        // band[jlo..jhi)

    const int bc = blockIdx.x >> 1;               // plane
    const int h  = blockIdx.x & 1;                // half: j in [h*256, h*256+256)
    const int c  = bc % C;
    const int tid = threadIdx.x;
    const float* plane = x + ((size_t)bc << 18);

    const int jlo = (h == 0) ? 0 : (h * 256 - 3);         // band range incl. halo
    const int jhi = (h == 0) ? 259 : S;
    const int r0  = (h == 0) ? 0 : (jlo - 10);            // stripe row range
    const int r1  = (h == 0) ? 269 : S;
    const int nrows = r1 - r0;

    // Phase 1: load stripe slice (contiguous 21-elem runs per row).
    const int total = nrows * BW;
    for (int idx = tid; idx < total; idx += 256) {
        const int rl  = idx / BW;
        const int k   = idx - rl * BW;
        const int r   = r0 + rl;
        const int col = r - HALF + k;
        stripe[idx] = (col >= 0 && col < S) ? plane[r * S + col] : 0.f;
    }
    __syncthreads();

    // Phase 2: band[j] = mean_t x[j-10+t, j] = stripe[(j-10+t-r0)*21 + (20-t)]
    for (int j = jlo + tid; j < jhi; j += 256) {
        float sum = 0.f;
        #pragma unroll
        for (int t = 0; t < BW; t++) {
            const int r = j - HALF + t;
            if (r >= 0 && r < S) sum += stripe[(r - r0) * BW + (BW - 1 - t)];
        }
        band_s[j - jlo] = sum * (1.0f / (float)BW);
    }
    __syncthreads();

    // Phase 3: depthwise conv1d k=7 pad=3 for j in [h*256, h*256+256)
    {
        float w[KS];
        #pragma unroll
        for (int k = 0; k < KS; k++) w[k] = conv_w[c * KS + k];
        const int j = h * 256 + tid;
        float acc = 0.f;
        #pragma unroll
        for (int k = 0; k < KS; k++) {
            const int jj = j + k - 3;
            if (jj >= 0 && jj < S) acc += band_s[jj - jlo] * w[k];
        }
        g_conv[(bc << 9) + j] = acc;
    }
}

// ---------------------------------------------------------------------------
// K2: tiled pointwise GEMV + softmax. Block = (batch b, d-tile of 8).
// 48 blocks x 512 threads; thread s owns 8 accumulators. Warp-shuffle
// reductions for softmax max/sum (4 __syncthreads total).
// ---------------------------------------------------------------------------
__global__ void __launch_bounds__(512) point_softmax_kernel(
        const float* __restrict__ point_w, const float* __restrict__ point_b) {
    __shared__ float wtile[8 * C];       // 6 KB
    __shared__ float part[16 * 8];       // per-warp partials
    __shared__ float bcast[8];

    const int blk = blockIdx.x;
    const int b   = blk / 24;
    const int g   = blk - b * 24;        // d-tile index, d in [g*8, g*8+8)
    const int s   = threadIdx.x;
    const int w   = s >> 5;              // warp 0..15
    const int lane = s & 31;

    for (int i = s; i < 8 * C; i += 512) {
        const int d = i / C, c = i - d * C;
        wtile[i] = point_w[(g * 8 + d) * C + c];
    }
    __syncthreads();

    const float* cb = g_conv + b * C * S + s;
    float acc[8];
    #pragma unroll
    for (int d = 0; d < 8; d++) acc[d] = point_b[g * 8 + d];

    for (int c = 0; c < C; c++) {
        const float v = cb[c * S];
        #pragma unroll
        for (int d = 0; d < 8; d++) acc[d] += v * wtile[d * C + c];
    }

    // ---- max over s (warp shuffle, then 16-partial smem reduce) ----
    float m[8];
    #pragma unroll
    for (int d = 0; d < 8; d++) {
        float v = acc[d];
        #pragma unroll
        for (int off = 16; off > 0; off >>= 1)
            v = fmaxf(v, __shfl_xor_sync(0xffffffffu, v, off));
        if (lane == 0) part[w * 8 + d] = v;
    }
    __syncthreads();
    if (s < 8) {
        float v = part[s];
        #pragma unroll
        for (int ww = 1; ww < 16; ww++) v = fmaxf(v, part[ww * 8 + s]);
        bcast[s] = v;
    }
    __syncthreads();
    #pragma unroll
    for (int d = 0; d < 8; d++) m[d] = bcast[d];
    __syncthreads();

    // ---- exp + sum over s ----
    float e[8];
    #pragma unroll
    for (int d = 0; d < 8; d++) {
        e[d] = __expf(acc[d] - m[d]);
        float v = e[d];
        #pragma unroll
        for (int off = 16; off > 0; off >>= 1)
            v += __shfl_xor_sync(0xffffffffu, v, off);
        if (lane == 0) part[w * 8 + d] = v;
    }
    __syncthreads();
    if (s < 8) {
        float v = part[s];
        #pragma unroll
        for (int ww = 1; ww < 16; ww++) v += part[ww * 8 + s];
        bcast[s] = 1.0f / v;
    }
    __syncthreads();

    #pragma unroll
    for (int d = 0; d < 8; d++)
        g_attn[(b * C + g * 8 + d) * S + s] = e[d] * bcast[d];
}

// ---------------------------------------------------------------------------
// K3: streaming copy x -> out (4 x float4 per thread, block-strided so every
// access is a full 128B line), scaling the main diagonal by attn.
// ---------------------------------------------------------------------------
__global__ void __launch_bounds__(256) copy_diag_kernel(
        const float4* __restrict__ x4, float4* __restrict__ out4) {
    const int tid  = threadIdx.x;
    const int base = blockIdx.x * 1024 + tid;

    float4 val[4];
    #pragma unroll
    for (int i = 0; i < 4; i++)
        val[i] = __ldcs(x4 + base + i * 256);

    #pragma unroll
    for (int i = 0; i < 4; i++) {
        const int v     = base + i * 256;
        const int e     = v << 2;          // element index (< 2^27)
        const int j0    = e & (S - 1);     // column of lane 0
        const int r     = (e >> 9) & (S - 1);
        const int plane = e >> 18;         // b*C + c
        const int dr    = r - j0;

        if ((unsigned)dr < 4u) {
            const float a = g_attn[(plane << 9) + r];
            if      (dr == 0) val[i].x *= a;
            else if (dr == 1) val[i].y *= a;
            else if (dr == 2) val[i].z *= a;
            else              val[i].w *= a;
        }
        __stcs(out4 + v, val[i]);
    }
}

// ---------------------------------------------------------------------------
extern "C" void kernel_launch(void* const* d_in, const int* in_sizes, int n_in,
                              void* d_out, int out_size) {
    const float* x       = (const float*)d_in[0];   // [2,192,512,512]
    const float* conv_w  = (const float*)d_in[1];   // [192,1,7]
    const float* point_w = (const float*)d_in[2];   // [192,192]
    const float* point_b = (const float*)d_in[3];   // [192]

    band_conv_kernel<<<NPLANES * 2, 256>>>(x, conv_w);
    point_softmax_kernel<<<48, 512>>>(point_w, point_b);

    const int n4     = out_size >> 2;     // 25,165,824 float4 (divisible by 1024)
    const int blocks = n4 >> 10;          // 24576 blocks, no tail
    copy_diag_kernel<<<blocks, 256>>>((const float4*)x, (float4*)d_out);
}

// round 6
// speedup vs baseline: 1.1859x; 1.0206x over previous
#include <cuda_runtime.h>

#define S    512
#define C    192
#define B    2
#define BW   21
#define HALF 10
#define KS   7

#define NPLANES (B * C)            // 384

// Scratch (allocation-free rule: __device__ globals)
__device__ float g_conv[NPLANES * S];   // band after depthwise conv
__device__ float g_attn[NPLANES * S];   // after pointwise + softmax

// ---------------------------------------------------------------------------
// K1: one block per (b,c) plane, 512 threads = 16 warps. Warp w owns columns
// [32w, 32w+32). band[j] = (1/21) * sum_{|r-j|<=10} x[r,j], computed by
// scanning 52 rows with fully-coalesced 128B row loads and a (t,lane)-only
// predicate. No staging smem; then k=7 depthwise conv via a 512-float smem.
// ---------------------------------------------------------------------------
__global__ void __launch_bounds__(512) band_conv_kernel(
        const float* __restrict__ x, const float* __restrict__ conv_w) {
    __shared__ float band_s[S];

    const int bc   = blockIdx.x;                  // b*C + c
    const int c    = bc % C;
    const int tid  = threadIdx.x;
    const int w    = tid >> 5;                    // warp 0..15
    const int lane = tid & 31;
    const int c0   = w << 5;                      // first column of this warp
    const int j    = c0 + lane;
    const float* plane = x + ((size_t)bc << 18);

    float sum = 0.f;
    #pragma unroll
    for (int t = -10; t <= 41; t++) {
        // lane needs row r=c0+t iff |t - lane| <= 10  (compile-time per t)
        if (t - 10 <= 31 && t + 10 >= 0) {        // any lane needs it (always true here)
            const int r = c0 + t;
            if (r >= 0 && r < S) {
                const float v = plane[r * S + j]; // coalesced 128B per warp
                const int d = t - lane;           // r - j
                if (d >= -10 && d <= 10) sum += v;
            }
        }
    }
    band_s[j] = sum * (1.0f / (float)BW);
    __syncthreads();

    // depthwise conv1d, k=7, pad=3 (cross-correlation, per channel)
    {
        float wgt[KS];
        #pragma unroll
        for (int k = 0; k < KS; k++) wgt[k] = conv_w[c * KS + k];
        float acc = 0.f;
        #pragma unroll
        for (int k = 0; k < KS; k++) {
            const int jj = j + k - 3;
            if (jj >= 0 && jj < S) acc += band_s[jj] * wgt[k];
        }
        g_conv[(bc << 9) + j] = acc;
    }
}

// ---------------------------------------------------------------------------
// K2: tiled pointwise GEMV + softmax. Block = (batch b, d-tile of 4).
// 96 blocks x 512 threads; thread s owns 4 accumulators (4x L2-traffic cut
// vs per-d blocks, 2x the parallelism of 8-wide tiles).
// ---------------------------------------------------------------------------
__global__ void __launch_bounds__(512) point_softmax_kernel(
        const float* __restrict__ point_w, const float* __restrict__ point_b) {
    __shared__ float wtile[4 * C];       // 3 KB
    __shared__ float part[16 * 4];
    __shared__ float bcast[4];

    const int blk  = blockIdx.x;
    const int b    = blk / 48;
    const int g    = blk - b * 48;       // d-tile, d in [4g, 4g+4)
    const int s    = threadIdx.x;
    const int w    = s >> 5;
    const int lane = s & 31;

    for (int i = s; i < 4 * C; i += 512) {
        const int d = i / C, cc = i - d * C;
        wtile[i] = point_w[(g * 4 + d) * C + cc];
    }
    __syncthreads();

    const float* cb = g_conv + b * C * S + s;
    float acc[4];
    #pragma unroll
    for (int d = 0; d < 4; d++) acc[d] = point_b[g * 4 + d];

    #pragma unroll 4
    for (int cc = 0; cc < C; cc++) {
        const float v = cb[cc * S];
        #pragma unroll
        for (int d = 0; d < 4; d++) acc[d] += v * wtile[d * C + cc];
    }

    // ---- max over s ----
    float m[4];
    #pragma unroll
    for (int d = 0; d < 4; d++) {
        float v = acc[d];
        #pragma unroll
        for (int off = 16; off > 0; off >>= 1)
            v = fmaxf(v, __shfl_xor_sync(0xffffffffu, v, off));
        if (lane == 0) part[w * 4 + d] = v;
    }
    __syncthreads();
    if (s < 4) {
        float v = part[s];
        #pragma unroll
        for (int ww = 1; ww < 16; ww++) v = fmaxf(v, part[ww * 4 + s]);
        bcast[s] = v;
    }
    __syncthreads();
    #pragma unroll
    for (int d = 0; d < 4; d++) m[d] = bcast[d];
    __syncthreads();

    // ---- exp + sum over s ----
    float e[4];
    #pragma unroll
    for (int d = 0; d < 4; d++) {
        e[d] = __expf(acc[d] - m[d]);
        float v = e[d];
        #pragma unroll
        for (int off = 16; off > 0; off >>= 1)
            v += __shfl_xor_sync(0xffffffffu, v, off);
        if (lane == 0) part[w * 4 + d] = v;
    }
    __syncthreads();
    if (s < 4) {
        float v = part[s];
        #pragma unroll
        for (int ww = 1; ww < 16; ww++) v += part[ww * 4 + s];
        bcast[s] = 1.0f / v;
    }
    __syncthreads();

    #pragma unroll
    for (int d = 0; d < 4; d++)
        g_attn[(b * C + g * 4 + d) * S + s] = e[d] * bcast[d];
}

// ---------------------------------------------------------------------------
// K3: streaming copy x -> out (4 x float4 per thread, block-strided so every
// access is a full 128B line), scaling the main diagonal by attn. (Proven.)
// ---------------------------------------------------------------------------
__global__ void __launch_bounds__(256) copy_diag_kernel(
        const float4* __restrict__ x4, float4* __restrict__ out4) {
    const int tid  = threadIdx.x;
    const int base = blockIdx.x * 1024 + tid;

    float4 val[4];
    #pragma unroll
    for (int i = 0; i < 4; i++)
        val[i] = __ldcs(x4 + base + i * 256);

    #pragma unroll
    for (int i = 0; i < 4; i++) {
        const int v     = base + i * 256;
        const int e     = v << 2;          // element index (< 2^27)
        const int j0    = e & (S - 1);     // column of lane 0
        const int r     = (e >> 9) & (S - 1);
        const int plane = e >> 18;         // b*C + c
        const int dr    = r - j0;

        if ((unsigned)dr < 4u) {
            const float a = g_attn[(plane << 9) + r];
            if      (dr == 0) val[i].x *= a;
            else if (dr == 1) val[i].y *= a;
            else if (dr == 2) val[i].z *= a;
            else              val[i].w *= a;
        }
        __stcs(out4 + v, val[i]);
    }
}

// ---------------------------------------------------------------------------
extern "C" void kernel_launch(void* const* d_in, const int* in_sizes, int n_in,
                              void* d_out, int out_size) {
    const float* x       = (const float*)d_in[0];   // [2,192,512,512]
    const float* conv_w  = (const float*)d_in[1];   // [192,1,7]
    const float* point_w = (const float*)d_in[2];   // [192,192]
    const float* point_b = (const float*)d_in[3];   // [192]

    band_conv_kernel<<<NPLANES, 512>>>(x, conv_w);
    point_softmax_kernel<<<96, 512>>>(point_w, point_b);

    const int n4     = out_size >> 2;     // 25,165,824 float4 (divisible by 1024)
    const int blocks = n4 >> 10;          // 24576 blocks, no tail
    copy_diag_kernel<<<blocks, 256>>>((const float4*)x, (float4*)d_out);
}